// round 10
// baseline (speedup 1.0000x reference)
#include <cuda_runtime.h>
#include <cuda_bf16.h>
#include <cstdint>

#define N_NODES 50000
#define N_EDGES 800000
#define D 128
#define N_LAYERS 3
#define N_GRAPHS 256

#define SCAN_BLK 256
#define SCAN_NBLK ((N_NODES + SCAN_BLK - 1) / SCAN_BLK)   // 196
#define MAXDEG_LOCAL 128

typedef unsigned long long ull;

// ---------------- scratch (static device globals) ---------------------------
__device__ float g_agg[N_NODES * D];
__device__ float g_h0[N_NODES * D];
__device__ float g_h1[N_NODES * D];
__device__ float g_norm_out[N_NODES];
__device__ float g_norm_in[N_NODES];
__device__ int   g_deg_out[N_NODES];
__device__ int   g_deg_in[N_NODES];
__device__ int   g_rowptr[N_NODES + 1];
__device__ int   g_cursor[N_NODES];
__device__ int   g_csr_src[N_EDGES];
__device__ int   g_blocksum[SCAN_NBLK];
__device__ int   g_blockoff[SCAN_NBLK];

// ---------------- packed f32x2 helpers (sm_100-family, non-'a') -------------
__device__ __forceinline__ ull pack_f32x2(float lo, float hi) {
    ull r;
    asm("mov.b64 %0, {%1, %2};" : "=l"(r) : "f"(lo), "f"(hi));
    return r;
}
__device__ __forceinline__ void unpack_f32x2(ull p, float& lo, float& hi) {
    asm("mov.b64 {%0, %1}, %2;" : "=f"(lo), "=f"(hi) : "l"(p));
}
#define FMA2(acc, a, b) \
    asm("fma.rn.f32x2 %0, %1, %2, %0;" : "+l"(acc) : "l"(a), "l"(b))

// ---------------- graph preprocessing --------------------------------------
__global__ void zero_deg_kernel() {
    int i = blockIdx.x * blockDim.x + threadIdx.x;
    if (i < N_NODES) { g_deg_out[i] = 0; g_deg_in[i] = 0; }
}

__global__ void count_deg_kernel(const int* __restrict__ src,
                                 const int* __restrict__ dst) {
    int t = blockIdx.x * blockDim.x + threadIdx.x;
    int base = t * 4;
    if (base + 3 < N_EDGES) {
        int4 s = *(const int4*)(src + base);
        int4 d = *(const int4*)(dst + base);
        atomicAdd(&g_deg_out[s.x], 1); atomicAdd(&g_deg_out[s.y], 1);
        atomicAdd(&g_deg_out[s.z], 1); atomicAdd(&g_deg_out[s.w], 1);
        atomicAdd(&g_deg_in[d.x], 1);  atomicAdd(&g_deg_in[d.y], 1);
        atomicAdd(&g_deg_in[d.z], 1);  atomicAdd(&g_deg_in[d.w], 1);
    } else {
        for (int i = base; i < N_EDGES; i++) {
            atomicAdd(&g_deg_out[src[i]], 1);
            atomicAdd(&g_deg_in[dst[i]], 1);
        }
    }
}

__global__ void scanA_kernel() {
    __shared__ int warp_sum[SCAN_BLK / 32];
    int i = blockIdx.x * SCAN_BLK + threadIdx.x;
    int v = 0;
    if (i < N_NODES) {
        int din = g_deg_in[i];
        v = din;
        g_norm_out[i] = rsqrtf((float)max(g_deg_out[i], 1));
        g_norm_in[i]  = rsqrtf((float)max(din, 1));
    }
    int s = v;
#pragma unroll
    for (int off = 16; off > 0; off >>= 1)
        s += __shfl_down_sync(0xffffffffu, s, off);
    if ((threadIdx.x & 31) == 0) warp_sum[threadIdx.x >> 5] = s;
    __syncthreads();
    if (threadIdx.x < SCAN_BLK / 32) {
        int ws = warp_sum[threadIdx.x];
#pragma unroll
        for (int off = SCAN_BLK / 64; off > 0; off >>= 1)
            ws += __shfl_down_sync(0xffffffffu, ws, off);
        if (threadIdx.x == 0) g_blocksum[blockIdx.x] = ws;
    }
}

__global__ void scanB_kernel() {
    __shared__ int sm[SCAN_NBLK];
    int t = threadIdx.x;
    int v = (t < SCAN_NBLK) ? g_blocksum[t] : 0;
    if (t < SCAN_NBLK) sm[t] = v;
    __syncthreads();
    for (int off = 1; off < SCAN_NBLK; off <<= 1) {
        int add = 0;
        if (t < SCAN_NBLK && t >= off) add = sm[t - off];
        __syncthreads();
        if (t < SCAN_NBLK && t >= off) sm[t] += add;
        __syncthreads();
    }
    if (t < SCAN_NBLK) g_blockoff[t] = sm[t] - v;
    if (t == 0) g_rowptr[N_NODES] = N_EDGES;
}

__global__ void scanC_kernel() {
    __shared__ int sm[SCAN_BLK];
    int i = blockIdx.x * SCAN_BLK + threadIdx.x;
    int t = threadIdx.x;
    int v = (i < N_NODES) ? g_deg_in[i] : 0;
    sm[t] = v;
    __syncthreads();
#pragma unroll
    for (int off = 1; off < SCAN_BLK; off <<= 1) {
        int add = (t >= off) ? sm[t - off] : 0;
        __syncthreads();
        sm[t] += add;
        __syncthreads();
    }
    if (i < N_NODES) {
        int rp = g_blockoff[blockIdx.x] + sm[t] - v;
        g_rowptr[i] = rp;
        g_cursor[i] = rp;
    }
}

__global__ void bucket_kernel(const int* __restrict__ src,
                              const int* __restrict__ dst) {
    int i = blockIdx.x * blockDim.x + threadIdx.x;
    if (i < N_EDGES) {
        int d = dst[i];
        int pos = atomicAdd(&g_cursor[d], 1);
        g_csr_src[pos] = src[i];
    }
}

__global__ void sort_csr_kernel() {
    int n = blockIdx.x * blockDim.x + threadIdx.x;
    if (n >= N_NODES) return;
    int beg = g_rowptr[n], end = g_rowptr[n + 1];
    int d = end - beg;
    if (d <= 1) return;
    if (d <= MAXDEG_LOCAL) {
        int buf[MAXDEG_LOCAL];
        for (int i = 0; i < d; i++) buf[i] = g_csr_src[beg + i];
        for (int i = 1; i < d; i++) {
            int v = buf[i];
            int j = i - 1;
            while (j >= 0 && buf[j] > v) { buf[j + 1] = buf[j]; j--; }
            buf[j + 1] = v;
        }
        for (int i = 0; i < d; i++) g_csr_src[beg + i] = buf[i];
    } else {
        for (int i = beg + 1; i < end; i++) {
            int v = g_csr_src[i];
            int j = i - 1;
            while (j >= beg && g_csr_src[j] > v) {
                g_csr_src[j + 1] = g_csr_src[j];
                j--;
            }
            g_csr_src[j + 1] = v;
        }
    }
}

// ---------------- SpMM ------------------------------------------------------
__global__ void spmm_kernel(const float* __restrict__ feats, int in_sel) {
    const float* __restrict__ in =
        (in_sel == 0) ? feats : ((in_sel == 1) ? g_h0 : g_h1);
    int gwarp = (blockIdx.x * blockDim.x + threadIdx.x) >> 5;
    int lane = threadIdx.x & 31;
    if (gwarp >= N_NODES) return;
    int beg = g_rowptr[gwarp], end = g_rowptr[gwarp + 1];
    float4 acc = make_float4(0.f, 0.f, 0.f, 0.f);
    int e = beg;
    for (; e + 3 < end; e += 4) {
        int s0 = g_csr_src[e],     s1 = g_csr_src[e + 1];
        int s2 = g_csr_src[e + 2], s3 = g_csr_src[e + 3];
        float w0 = g_norm_out[s0], w1 = g_norm_out[s1];
        float w2 = g_norm_out[s2], w3 = g_norm_out[s3];
        float4 v0 = ((const float4*)(in + s0 * D))[lane];
        float4 v1 = ((const float4*)(in + s1 * D))[lane];
        float4 v2 = ((const float4*)(in + s2 * D))[lane];
        float4 v3 = ((const float4*)(in + s3 * D))[lane];
        acc.x += w0 * v0.x + w1 * v1.x + w2 * v2.x + w3 * v3.x;
        acc.y += w0 * v0.y + w1 * v1.y + w2 * v2.y + w3 * v3.y;
        acc.z += w0 * v0.z + w1 * v1.z + w2 * v2.z + w3 * v3.z;
        acc.w += w0 * v0.w + w1 * v1.w + w2 * v2.w + w3 * v3.w;
    }
    for (; e < end; e++) {
        int s0 = g_csr_src[e];
        float w0 = g_norm_out[s0];
        float4 v0 = ((const float4*)(in + s0 * D))[lane];
        acc.x += w0 * v0.x; acc.y += w0 * v0.y;
        acc.z += w0 * v0.z; acc.w += w0 * v0.w;
    }
    float ni = g_norm_in[gwarp];
    acc.x *= ni; acc.y *= ni; acc.z *= ni; acc.w *= ni;
    ((float4*)(g_agg + gwarp * D))[lane] = acc;
}

// ---------------- GEMM + bias + relu via packed f32x2 -----------------------
// block = 256 thr, tile = 64 rows x 128 cols. Thread: 8 rows x 4 cols.
// acc pair halves hold even-k / odd-k partial sums (exact fp32, summed at end).
__global__ void __launch_bounds__(256, 2)
gemm_f32x2_kernel(const float* __restrict__ Wl, const float* __restrict__ bl,
                  int out_sel) {
    __shared__ float As[64][D];   // row-major; rows 512B -> 8B-aligned pairs
    float* __restrict__ outp = (out_sel == 0) ? g_h0 : g_h1;
    int row0 = blockIdx.x * 64;
    int nrows = N_NODES - row0;
    if (nrows > 64) nrows = 64;

    // load A tile: 64 rows x 32 float4 = 2048 float4, 8 per thread
    for (int idx = threadIdx.x; idx < 64 * 32; idx += 256) {
        int r = idx >> 5;
        int c4 = idx & 31;
        float4 v = (r < nrows)
                       ? ((const float4*)(g_agg + (size_t)(row0 + r) * D))[c4]
                       : make_float4(0.f, 0.f, 0.f, 0.f);
        *((float4*)&As[r][c4 * 4]) = v;
    }
    __syncthreads();

    int wid = threadIdx.x >> 5;      // 0..7 -> 8-row group (uniform per warp)
    int tx  = threadIdx.x & 31;      // 0..31 -> float4 column group
    int r = wid * 8;

    ull acc[8][4];
#pragma unroll
    for (int i = 0; i < 8; i++)
#pragma unroll
        for (int j = 0; j < 4; j++) acc[i][j] = 0ull;

    const float4* __restrict__ Wv = (const float4*)Wl;

#pragma unroll 4
    for (int k2 = 0; k2 < D / 2; k2++) {
        // w rows k=2*k2 and 2*k2+1, this thread's 4 cols (coalesced)
        float4 wk  = __ldg(&Wv[(2 * k2 + 0) * 32 + tx]);
        float4 wk1 = __ldg(&Wv[(2 * k2 + 1) * 32 + tx]);
        ull wp0 = pack_f32x2(wk.x, wk1.x);
        ull wp1 = pack_f32x2(wk.y, wk1.y);
        ull wp2 = pack_f32x2(wk.z, wk1.z);
        ull wp3 = pack_f32x2(wk.w, wk1.w);
#pragma unroll
        for (int i = 0; i < 8; i++) {
            // (a_{2k2}, a_{2k2+1}) adjacent in smem row -> one 8B broadcast ld
            ull ap = *(const ull*)&As[r + i][2 * k2];
            FMA2(acc[i][0], ap, wp0);
            FMA2(acc[i][1], ap, wp1);
            FMA2(acc[i][2], ap, wp2);
            FMA2(acc[i][3], ap, wp3);
        }
    }

    float4 bb = __ldg(&((const float4*)bl)[tx]);
#pragma unroll
    for (int i = 0; i < 8; i++) {
        int gr = row0 + r + i;
        if (gr < N_NODES) {
            float lo, hi;
            float4 v;
            unpack_f32x2(acc[i][0], lo, hi); v.x = fmaxf(lo + hi + bb.x, 0.f);
            unpack_f32x2(acc[i][1], lo, hi); v.y = fmaxf(lo + hi + bb.y, 0.f);
            unpack_f32x2(acc[i][2], lo, hi); v.z = fmaxf(lo + hi + bb.z, 0.f);
            unpack_f32x2(acc[i][3], lo, hi); v.w = fmaxf(lo + hi + bb.w, 0.f);
            ((float4*)(outp + (size_t)gr * D))[tx] = v;
        }
    }
}

// ---------------- pooling ---------------------------------------------------
__device__ __forceinline__ int lower_bound_dev(const int* __restrict__ a,
                                               int n, int key) {
    int lo = 0, hi = n;
    while (lo < hi) {
        int mid = (lo + hi) >> 1;
        if (a[mid] < key) lo = mid + 1; else hi = mid;
    }
    return lo;
}

__global__ void pool_kernel(const int* __restrict__ gid,
                            float* __restrict__ out) {
    __shared__ int s_beg, s_end;
    int g = blockIdx.x;
    if (threadIdx.x == 0) {
        s_beg = lower_bound_dev(gid, N_NODES, g);
        s_end = lower_bound_dev(gid, N_NODES, g + 1);
    }
    __syncthreads();
    int beg = s_beg, end = s_end;
    const float* __restrict__ h = g_h0;
    float acc = 0.f;
    for (int n = beg; n < end; n++) acc += h[n * D + threadIdx.x];
    float cnt = (float)max(end - beg, 1);
    out[g * D + threadIdx.x] = acc / cnt;
}

// ---------------- launch ----------------------------------------------------
extern "C" void kernel_launch(void* const* d_in, const int* in_sizes, int n_in,
                              void* d_out, int out_size) {
    const float* feats = (const float*)d_in[0];
    const float* W     = (const float*)d_in[1];
    const float* b     = (const float*)d_in[2];
    const int*   src   = (const int*)d_in[3];
    const int*   dst   = (const int*)d_in[4];
    const int*   gid   = (const int*)d_in[5];
    float* out = (float*)d_out;

    const int NODE_BLKS = (N_NODES + 255) / 256;           // 196
    const int EDGE_BLKS = (N_EDGES + 255) / 256;           // 3125
    const int CNT_BLKS  = (N_EDGES / 4 + 255) / 256;       // 782

    zero_deg_kernel<<<NODE_BLKS, 256>>>();
    count_deg_kernel<<<CNT_BLKS, 256>>>(src, dst);
    scanA_kernel<<<SCAN_NBLK, SCAN_BLK>>>();
    scanB_kernel<<<1, 256>>>();
    scanC_kernel<<<SCAN_NBLK, SCAN_BLK>>>();
    bucket_kernel<<<EDGE_BLKS, 256>>>(src, dst);
    sort_csr_kernel<<<NODE_BLKS, 256>>>();

    const int SPMM_BLKS = N_NODES / 8;                     // 6250
    const int GEMM_BLKS = (N_NODES + 63) / 64;             // 782

    spmm_kernel<<<SPMM_BLKS, 256>>>(feats, 0);
    gemm_f32x2_kernel<<<GEMM_BLKS, 256>>>(W + 0 * D * D, b + 0 * D, 0);
    spmm_kernel<<<SPMM_BLKS, 256>>>(feats, 1);
    gemm_f32x2_kernel<<<GEMM_BLKS, 256>>>(W + 1 * D * D, b + 1 * D, 1);
    spmm_kernel<<<SPMM_BLKS, 256>>>(feats, 2);
    gemm_f32x2_kernel<<<GEMM_BLKS, 256>>>(W + 2 * D * D, b + 2 * D, 0);

    pool_kernel<<<N_GRAPHS, 128>>>(gid, out);
}

// round 11
// speedup vs baseline: 1.3464x; 1.3464x over previous
#include <cuda_runtime.h>
#include <cuda_bf16.h>
#include <cstdint>

#define N_NODES 50000
#define N_EDGES 800000
#define D 128
#define N_LAYERS 3
#define N_GRAPHS 256

#define SCAN_BLK 256
#define SCAN_NBLK ((N_NODES + SCAN_BLK - 1) / SCAN_BLK)   // 196
#define MAXDEG_LOCAL 128

// ---------------- scratch (static device globals) ---------------------------
__device__ float g_agg[N_NODES * D];
__device__ float g_h0[N_NODES * D];
__device__ float g_h1[N_NODES * D];
__device__ float g_norm_out[N_NODES];
__device__ float g_norm_in[N_NODES];
__device__ int   g_deg_out[N_NODES];
__device__ int   g_deg_in[N_NODES];
__device__ int   g_rowptr[N_NODES + 1];
__device__ int   g_cursor[N_NODES];
__device__ int   g_csr_src[N_EDGES];
__device__ int   g_blocksum[SCAN_NBLK];
__device__ int   g_blockoff[SCAN_NBLK];

// ---------------- graph preprocessing --------------------------------------
__global__ void zero_deg_kernel() {
    int i = blockIdx.x * blockDim.x + threadIdx.x;
    if (i < N_NODES) { g_deg_out[i] = 0; g_deg_in[i] = 0; }
}

__global__ void count_deg_kernel(const int* __restrict__ src,
                                 const int* __restrict__ dst) {
    int t = blockIdx.x * blockDim.x + threadIdx.x;
    int base = t * 4;
    if (base + 3 < N_EDGES) {
        int4 s = *(const int4*)(src + base);
        int4 d = *(const int4*)(dst + base);
        atomicAdd(&g_deg_out[s.x], 1); atomicAdd(&g_deg_out[s.y], 1);
        atomicAdd(&g_deg_out[s.z], 1); atomicAdd(&g_deg_out[s.w], 1);
        atomicAdd(&g_deg_in[d.x], 1);  atomicAdd(&g_deg_in[d.y], 1);
        atomicAdd(&g_deg_in[d.z], 1);  atomicAdd(&g_deg_in[d.w], 1);
    } else {
        for (int i = base; i < N_EDGES; i++) {
            atomicAdd(&g_deg_out[src[i]], 1);
            atomicAdd(&g_deg_in[dst[i]], 1);
        }
    }
}

__global__ void scanA_kernel() {
    __shared__ int warp_sum[SCAN_BLK / 32];
    int i = blockIdx.x * SCAN_BLK + threadIdx.x;
    int v = 0;
    if (i < N_NODES) {
        int din = g_deg_in[i];
        v = din;
        g_norm_out[i] = rsqrtf((float)max(g_deg_out[i], 1));
        g_norm_in[i]  = rsqrtf((float)max(din, 1));
    }
    int s = v;
#pragma unroll
    for (int off = 16; off > 0; off >>= 1)
        s += __shfl_down_sync(0xffffffffu, s, off);
    if ((threadIdx.x & 31) == 0) warp_sum[threadIdx.x >> 5] = s;
    __syncthreads();
    if (threadIdx.x < SCAN_BLK / 32) {
        int ws = warp_sum[threadIdx.x];
#pragma unroll
        for (int off = SCAN_BLK / 64; off > 0; off >>= 1)
            ws += __shfl_down_sync(0xffffffffu, ws, off);
        if (threadIdx.x == 0) g_blocksum[blockIdx.x] = ws;
    }
}

__global__ void scanB_kernel() {
    __shared__ int sm[SCAN_NBLK];
    int t = threadIdx.x;
    int v = (t < SCAN_NBLK) ? g_blocksum[t] : 0;
    if (t < SCAN_NBLK) sm[t] = v;
    __syncthreads();
    for (int off = 1; off < SCAN_NBLK; off <<= 1) {
        int add = 0;
        if (t < SCAN_NBLK && t >= off) add = sm[t - off];
        __syncthreads();
        if (t < SCAN_NBLK && t >= off) sm[t] += add;
        __syncthreads();
    }
    if (t < SCAN_NBLK) g_blockoff[t] = sm[t] - v;
    if (t == 0) g_rowptr[N_NODES] = N_EDGES;
}

__global__ void scanC_kernel() {
    __shared__ int sm[SCAN_BLK];
    int i = blockIdx.x * SCAN_BLK + threadIdx.x;
    int t = threadIdx.x;
    int v = (i < N_NODES) ? g_deg_in[i] : 0;
    sm[t] = v;
    __syncthreads();
#pragma unroll
    for (int off = 1; off < SCAN_BLK; off <<= 1) {
        int add = (t >= off) ? sm[t - off] : 0;
        __syncthreads();
        sm[t] += add;
        __syncthreads();
    }
    if (i < N_NODES) {
        int rp = g_blockoff[blockIdx.x] + sm[t] - v;
        g_rowptr[i] = rp;
        g_cursor[i] = rp;
    }
}

__global__ void bucket_kernel(const int* __restrict__ src,
                              const int* __restrict__ dst) {
    int i = blockIdx.x * blockDim.x + threadIdx.x;
    if (i < N_EDGES) {
        int d = dst[i];
        int pos = atomicAdd(&g_cursor[d], 1);
        g_csr_src[pos] = src[i];
    }
}

__global__ void sort_csr_kernel() {
    int n = blockIdx.x * blockDim.x + threadIdx.x;
    if (n >= N_NODES) return;
    int beg = g_rowptr[n], end = g_rowptr[n + 1];
    int d = end - beg;
    if (d <= 1) return;
    if (d <= MAXDEG_LOCAL) {
        int buf[MAXDEG_LOCAL];
        for (int i = 0; i < d; i++) buf[i] = g_csr_src[beg + i];
        for (int i = 1; i < d; i++) {
            int v = buf[i];
            int j = i - 1;
            while (j >= 0 && buf[j] > v) { buf[j + 1] = buf[j]; j--; }
            buf[j + 1] = v;
        }
        for (int i = 0; i < d; i++) g_csr_src[beg + i] = buf[i];
    } else {
        for (int i = beg + 1; i < end; i++) {
            int v = g_csr_src[i];
            int j = i - 1;
            while (j >= beg && g_csr_src[j] > v) {
                g_csr_src[j + 1] = g_csr_src[j];
                j--;
            }
            g_csr_src[j + 1] = v;
        }
    }
}

// ---------------- SpMM ------------------------------------------------------
__global__ void spmm_kernel(const float* __restrict__ feats, int in_sel) {
    const float* __restrict__ in =
        (in_sel == 0) ? feats : ((in_sel == 1) ? g_h0 : g_h1);
    int gwarp = (blockIdx.x * blockDim.x + threadIdx.x) >> 5;
    int lane = threadIdx.x & 31;
    if (gwarp >= N_NODES) return;
    int beg = g_rowptr[gwarp], end = g_rowptr[gwarp + 1];
    float4 acc = make_float4(0.f, 0.f, 0.f, 0.f);
    int e = beg;
    for (; e + 3 < end; e += 4) {
        int s0 = g_csr_src[e],     s1 = g_csr_src[e + 1];
        int s2 = g_csr_src[e + 2], s3 = g_csr_src[e + 3];
        float w0 = g_norm_out[s0], w1 = g_norm_out[s1];
        float w2 = g_norm_out[s2], w3 = g_norm_out[s3];
        float4 v0 = ((const float4*)(in + s0 * D))[lane];
        float4 v1 = ((const float4*)(in + s1 * D))[lane];
        float4 v2 = ((const float4*)(in + s2 * D))[lane];
        float4 v3 = ((const float4*)(in + s3 * D))[lane];
        acc.x += w0 * v0.x + w1 * v1.x + w2 * v2.x + w3 * v3.x;
        acc.y += w0 * v0.y + w1 * v1.y + w2 * v2.y + w3 * v3.y;
        acc.z += w0 * v0.z + w1 * v1.z + w2 * v2.z + w3 * v3.z;
        acc.w += w0 * v0.w + w1 * v1.w + w2 * v2.w + w3 * v3.w;
    }
    for (; e < end; e++) {
        int s0 = g_csr_src[e];
        float w0 = g_norm_out[s0];
        float4 v0 = ((const float4*)(in + s0 * D))[lane];
        acc.x += w0 * v0.x; acc.y += w0 * v0.y;
        acc.z += w0 * v0.z; acc.w += w0 * v0.w;
    }
    float ni = g_norm_in[gwarp];
    acc.x *= ni; acc.y *= ni; acc.z *= ni; acc.w *= ni;
    ((float4*)(g_agg + gwarp * D))[lane] = acc;
}

// ---------------- GEMM via mma.sync bf16 (hi/lo split) + bias + relu --------
// block = 128 thr (4 warps), tile 64 rows x 128 cols.
// Warp (wm,wn): 32 rows x 64 cols = 2 m-tiles(16) x 8 n-tiles(8), K=128.
// D = A@W in 3 bf16 passes per k-chunk: AhiBhi + AloBhi + AhiBlo (fp32 acc).
#define AS_STRB 272                     // 136 bf16 per row (8-elt pad)
#define SM_AHI  0
#define SM_ALO  (SM_AHI + 64 * AS_STRB)     // 17408
#define SM_BHI  (SM_ALO + 64 * AS_STRB)     // 34816
#define SM_BLO  (SM_BHI + 128 * AS_STRB)    // 69632
#define SM_TOT  (SM_BLO + 128 * AS_STRB)    // 104448

__device__ __forceinline__ void mma_bf16(float* c, const uint32_t* a,
                                         uint32_t b0, uint32_t b1) {
    asm volatile(
        "mma.sync.aligned.m16n8k16.row.col.f32.bf16.bf16.f32 "
        "{%0,%1,%2,%3}, {%4,%5,%6,%7}, {%8,%9}, {%0,%1,%2,%3};"
        : "+f"(c[0]), "+f"(c[1]), "+f"(c[2]), "+f"(c[3])
        : "r"(a[0]), "r"(a[1]), "r"(a[2]), "r"(a[3]), "r"(b0), "r"(b1));
}

__device__ __forceinline__ void split_bf16x8(const float* xs,
                                             __nv_bfloat16* hi,
                                             __nv_bfloat16* lo) {
#pragma unroll
    for (int j = 0; j < 8; j++) {
        hi[j] = __float2bfloat16(xs[j]);
        lo[j] = __float2bfloat16(xs[j] - __bfloat162float(hi[j]));
    }
}

__global__ void __launch_bounds__(128, 2)
gemm_mma_kernel(const float* __restrict__ Wl, const float* __restrict__ bl,
                int out_sel) {
    extern __shared__ char smem[];
    float* __restrict__ outp = (out_sel == 0) ? g_h0 : g_h1;
    const int tid = threadIdx.x;
    const int wid = tid >> 5, lane = tid & 31;
    const int row0 = blockIdx.x * 64;

    // --- stage A tile: thread t -> row t/2, col-half t&1 --------------------
    {
        int r = tid >> 1, ch = tid & 1;
        int grow = row0 + r;
        bool valid = grow < N_NODES;
        const float4* __restrict__ arow =
            (const float4*)(g_agg + (size_t)(valid ? grow : 0) * D);
#pragma unroll
        for (int j0 = 0; j0 < 64; j0 += 8) {
            int c = ch * 64 + j0;
            float4 f0 = valid ? arow[c / 4]     : make_float4(0.f, 0.f, 0.f, 0.f);
            float4 f1 = valid ? arow[c / 4 + 1] : make_float4(0.f, 0.f, 0.f, 0.f);
            float xs[8] = {f0.x, f0.y, f0.z, f0.w, f1.x, f1.y, f1.z, f1.w};
            __nv_bfloat16 hi[8], lo[8];
            split_bf16x8(xs, hi, lo);
            *(uint4*)(smem + SM_AHI + r * AS_STRB + c * 2) = *(uint4*)hi;
            *(uint4*)(smem + SM_ALO + r * AS_STRB + c * 2) = *(uint4*)lo;
        }
    }

    // --- stage B = W^T (n-major): thread t -> n row t -----------------------
    {
        int n = tid;
#pragma unroll
        for (int k0 = 0; k0 < D; k0 += 8) {
            float xs[8];
#pragma unroll
            for (int j = 0; j < 8; j++) xs[j] = __ldg(Wl + (k0 + j) * D + n);
            __nv_bfloat16 hi[8], lo[8];
            split_bf16x8(xs, hi, lo);
            *(uint4*)(smem + SM_BHI + n * AS_STRB + k0 * 2) = *(uint4*)hi;
            *(uint4*)(smem + SM_BLO + n * AS_STRB + k0 * 2) = *(uint4*)lo;
        }
    }
    __syncthreads();

    // --- main loop ----------------------------------------------------------
    const int wm = wid & 1;        // row half (0/1) -> +32 rows
    const int wn = wid >> 1;       // col half (0/1) -> +64 cols
    const int r4 = lane >> 2;      // 0..7
    const int q  = lane & 3;       // 0..3

    float acc[2][8][4];
#pragma unroll
    for (int mt = 0; mt < 2; mt++)
#pragma unroll
        for (int nt = 0; nt < 8; nt++)
#pragma unroll
            for (int j = 0; j < 4; j++) acc[mt][nt][j] = 0.f;

    const char* As_hi = smem + SM_AHI;
    const char* As_lo = smem + SM_ALO;
    const char* Bs_hi = smem + SM_BHI;
    const char* Bs_lo = smem + SM_BLO;

#pragma unroll 2
    for (int kc = 0; kc < 8; kc++) {
        int k0 = kc * 16;
        uint32_t ah[2][4], al[2][4];
#pragma unroll
        for (int mt = 0; mt < 2; mt++) {
            int rm = wm * 32 + mt * 16 + r4;
            int ka = k0 + 2 * q;
            ah[mt][0] = *(const uint32_t*)(As_hi + rm * AS_STRB + ka * 2);
            ah[mt][1] = *(const uint32_t*)(As_hi + (rm + 8) * AS_STRB + ka * 2);
            ah[mt][2] = *(const uint32_t*)(As_hi + rm * AS_STRB + (ka + 8) * 2);
            ah[mt][3] = *(const uint32_t*)(As_hi + (rm + 8) * AS_STRB + (ka + 8) * 2);
            al[mt][0] = *(const uint32_t*)(As_lo + rm * AS_STRB + ka * 2);
            al[mt][1] = *(const uint32_t*)(As_lo + (rm + 8) * AS_STRB + ka * 2);
            al[mt][2] = *(const uint32_t*)(As_lo + rm * AS_STRB + (ka + 8) * 2);
            al[mt][3] = *(const uint32_t*)(As_lo + (rm + 8) * AS_STRB + (ka + 8) * 2);
        }
#pragma unroll
        for (int nt = 0; nt < 8; nt++) {
            int nn = wn * 64 + nt * 8 + r4;
            int kb = k0 + 2 * q;
            uint32_t bh0 = *(const uint32_t*)(Bs_hi + nn * AS_STRB + kb * 2);
            uint32_t bh1 = *(const uint32_t*)(Bs_hi + nn * AS_STRB + (kb + 8) * 2);
            uint32_t bl0 = *(const uint32_t*)(Bs_lo + nn * AS_STRB + kb * 2);
            uint32_t bl1 = *(const uint32_t*)(Bs_lo + nn * AS_STRB + (kb + 8) * 2);
#pragma unroll
            for (int mt = 0; mt < 2; mt++) {
                mma_bf16(acc[mt][nt], ah[mt], bh0, bh1);
                mma_bf16(acc[mt][nt], al[mt], bh0, bh1);
                mma_bf16(acc[mt][nt], ah[mt], bl0, bl1);
            }
        }
    }

    // --- epilogue: bias + relu, float2 stores -------------------------------
#pragma unroll
    for (int mt = 0; mt < 2; mt++) {
#pragma unroll
        for (int nt = 0; nt < 8; nt++) {
            int row = row0 + wm * 32 + mt * 16 + r4;
            int col = wn * 64 + nt * 8 + 2 * q;
            float2 bb = *(const float2*)(bl + col);
            if (row < N_NODES) {
                float2 v;
                v.x = fmaxf(acc[mt][nt][0] + bb.x, 0.f);
                v.y = fmaxf(acc[mt][nt][1] + bb.y, 0.f);
                *(float2*)(outp + (size_t)row * D + col) = v;
            }
            if (row + 8 < N_NODES) {
                float2 v;
                v.x = fmaxf(acc[mt][nt][2] + bb.x, 0.f);
                v.y = fmaxf(acc[mt][nt][3] + bb.y, 0.f);
                *(float2*)(outp + (size_t)(row + 8) * D + col) = v;
            }
        }
    }
}

// ---------------- pooling ---------------------------------------------------
__device__ __forceinline__ int lower_bound_dev(const int* __restrict__ a,
                                               int n, int key) {
    int lo = 0, hi = n;
    while (lo < hi) {
        int mid = (lo + hi) >> 1;
        if (a[mid] < key) lo = mid + 1; else hi = mid;
    }
    return lo;
}

__global__ void pool_kernel(const int* __restrict__ gid,
                            float* __restrict__ out) {
    __shared__ int s_beg, s_end;
    int g = blockIdx.x;
    if (threadIdx.x == 0) {
        s_beg = lower_bound_dev(gid, N_NODES, g);
        s_end = lower_bound_dev(gid, N_NODES, g + 1);
    }
    __syncthreads();
    int beg = s_beg, end = s_end;
    const float* __restrict__ h = g_h0;
    float acc = 0.f;
    for (int n = beg; n < end; n++) acc += h[n * D + threadIdx.x];
    float cnt = (float)max(end - beg, 1);
    out[g * D + threadIdx.x] = acc / cnt;
}

// ---------------- launch ----------------------------------------------------
extern "C" void kernel_launch(void* const* d_in, const int* in_sizes, int n_in,
                              void* d_out, int out_size) {
    const float* feats = (const float*)d_in[0];
    const float* W     = (const float*)d_in[1];
    const float* b     = (const float*)d_in[2];
    const int*   src   = (const int*)d_in[3];
    const int*   dst   = (const int*)d_in[4];
    const int*   gid   = (const int*)d_in[5];
    float* out = (float*)d_out;

    cudaFuncSetAttribute(gemm_mma_kernel,
                         cudaFuncAttributeMaxDynamicSharedMemorySize, SM_TOT);

    const int NODE_BLKS = (N_NODES + 255) / 256;           // 196
    const int EDGE_BLKS = (N_EDGES + 255) / 256;           // 3125
    const int CNT_BLKS  = (N_EDGES / 4 + 255) / 256;       // 782

    zero_deg_kernel<<<NODE_BLKS, 256>>>();
    count_deg_kernel<<<CNT_BLKS, 256>>>(src, dst);
    scanA_kernel<<<SCAN_NBLK, SCAN_BLK>>>();
    scanB_kernel<<<1, 256>>>();
    scanC_kernel<<<SCAN_NBLK, SCAN_BLK>>>();
    bucket_kernel<<<EDGE_BLKS, 256>>>(src, dst);
    sort_csr_kernel<<<NODE_BLKS, 256>>>();

    const int SPMM_BLKS = N_NODES / 8;                     // 6250
    const int GEMM_BLKS = (N_NODES + 63) / 64;             // 782

    spmm_kernel<<<SPMM_BLKS, 256>>>(feats, 0);
    gemm_mma_kernel<<<GEMM_BLKS, 128, SM_TOT>>>(W + 0 * D * D, b + 0 * D, 0);
    spmm_kernel<<<SPMM_BLKS, 256>>>(feats, 1);
    gemm_mma_kernel<<<GEMM_BLKS, 128, SM_TOT>>>(W + 1 * D * D, b + 1 * D, 1);
    spmm_kernel<<<SPMM_BLKS, 256>>>(feats, 2);
    gemm_mma_kernel<<<GEMM_BLKS, 128, SM_TOT>>>(W + 2 * D * D, b + 2 * D, 0);

    pool_kernel<<<N_GRAPHS, 128>>>(gid, out);
}